// round 12
// baseline (speedup 1.0000x reference)
#include <cuda_runtime.h>
#include <cuda_fp16.h>
#include <math.h>
#include <stdint.h>

#define N_TOK 32768
#define M_CODE 4096
#define D_DIM 256
#define M_TILE 128                    // tokens per CTA
#define NT 128                        // codes per tile
#define CT_COUNT (M_CODE / NT)        // 32
#define KC 64                         // k per chunk
#define CHUNKS (CT_COUNT * 4)         // 128 chunks of 64 k
#define NTHREADS 512

// ---------------- smem layout (bytes) ----------------
#define A_PITCH 264                    // halves per row (256 + 8 pad)
#define A_SPLIT 67584                  // 128 * 264 * 2
#define SM_A    0                      // [2 splits][128 rows][264 halves]
#define SM_B    135168                 // 4 wn-group slices
#define B_PITCHB 144                   // bytes per row (128 + 16 pad)
#define B_SPLIT 4608                   // 32 rows * 144
#define B_BUF   9216                   // 2 splits
#define B_SLICE 18432                  // 2 buffers
#define SM_FIDX 208896                 // 128 ints
#define SMEM_TOTAL 209408

__device__ float g_e2[M_CODE];
__device__ int   g_counts[M_CODE];
__device__ float g_loss_sum;
__device__ __align__(16) __half g_eh[M_CODE * D_DIM];
__device__ __align__(16) __half g_el[M_CODE * D_DIM];

// ---------------------------- helpers ----------------------------------
__device__ __forceinline__ uint32_t smem_u32(const void* p) {
    uint32_t a;
    asm("{ .reg .u64 t; cvta.to.shared.u64 t, %1; cvt.u32.u64 %0, t; }"
        : "=r"(a) : "l"(p));
    return a;
}
__device__ __forceinline__ void ldsm_x4(uint32_t& r0, uint32_t& r1,
                                        uint32_t& r2, uint32_t& r3, uint32_t a) {
    asm volatile("ldmatrix.sync.aligned.m8n8.x4.shared.b16 {%0,%1,%2,%3}, [%4];"
                 : "=r"(r0), "=r"(r1), "=r"(r2), "=r"(r3) : "r"(a));
}
__device__ __forceinline__ void cp16(uint32_t dst, const void* src) {
    asm volatile("cp.async.cg.shared.global [%0], [%1], 16;"
                 :: "r"(dst), "l"(src) : "memory");
}
__device__ __forceinline__ void cp_commit() {
    asm volatile("cp.async.commit_group;" ::: "memory");
}
__device__ __forceinline__ void cp_wait1() {
    asm volatile("cp.async.wait_group 1;" ::: "memory");
}
__device__ __forceinline__ void bar_grp(int id) {
    asm volatile("bar.sync %0, 128;" :: "r"(id) : "memory");
}
__device__ __forceinline__ void mma16816(float* c, const uint32_t* a, const uint32_t* b) {
    asm volatile(
        "mma.sync.aligned.m16n8k16.row.col.f32.f16.f16.f32 "
        "{%0,%1,%2,%3}, {%4,%5,%6,%7}, {%8,%9}, {%0,%1,%2,%3};"
        : "+f"(c[0]), "+f"(c[1]), "+f"(c[2]), "+f"(c[3])
        : "r"(a[0]), "r"(a[1]), "r"(a[2]), "r"(a[3]), "r"(b[0]), "r"(b[1]));
}

// ----------------------------- small kernels --------------------------------
__global__ void vq_init_kernel() {
    int t = blockIdx.x * blockDim.x + threadIdx.x;
    if (t < M_CODE) g_counts[t] = 0;
    if (t == 0) g_loss_sum = 0.0f;
}
__global__ void vq_e2_kernel(const float* __restrict__ embed) {
    int m = blockIdx.x * blockDim.x + threadIdx.x;
    if (m >= M_CODE) return;
    const float4* row = reinterpret_cast<const float4*>(embed + (size_t)m * D_DIM);
    float s = 0.0f;
#pragma unroll
    for (int i = 0; i < D_DIM / 4; i++) {
        float4 v = row[i];
        s += v.x * v.x + v.y * v.y + v.z * v.z + v.w * v.w;
    }
    g_e2[m] = s;
}
__global__ void vq_split_kernel(const float* __restrict__ embed) {
    int i = blockIdx.x * blockDim.x + threadIdx.x;   // one float4 each
    if (i >= M_CODE * D_DIM / 4) return;
    float4 v = reinterpret_cast<const float4*>(embed)[i];
    __half hx = __float2half_rn(v.x), hy = __float2half_rn(v.y);
    __half hz = __float2half_rn(v.z), hw = __float2half_rn(v.w);
    __half lx = __float2half_rn(v.x - __half2float(hx));
    __half ly = __float2half_rn(v.y - __half2float(hy));
    __half lz = __float2half_rn(v.z - __half2float(hz));
    __half lw = __float2half_rn(v.w - __half2float(hw));
    half2* ph = reinterpret_cast<half2*>(g_eh);
    half2* pl = reinterpret_cast<half2*>(g_el);
    ph[i * 2 + 0] = __halves2half2(hx, hy);
    ph[i * 2 + 1] = __halves2half2(hz, hw);
    pl[i * 2 + 0] = __halves2half2(lx, ly);
    pl[i * 2 + 1] = __halves2half2(lz, lw);
}

// ------------------------------ main kernel ---------------------------------
__global__ __launch_bounds__(NTHREADS, 1)
void vq_main_kernel(const float* __restrict__ x,
                    const float* __restrict__ embed,
                    float* __restrict__ quant_out,
                    float* __restrict__ idx_out) {
    extern __shared__ char smem[];
    const uint32_t sb = smem_u32(smem);
    const int tid = threadIdx.x;
    const int lane = tid & 31;
    const int wid = tid >> 5;
    const int wn = wid & 3;              // col stripe wn*32 .. +32
    const int wm = wid >> 2;             // row stripe wm*32 .. +32
    const int row0 = blockIdx.x * M_TILE;
    const int barid = wn + 1;            // named barrier per wn-group (4 warps)

    int* fidx = (int*)(smem + SM_FIDX);
    const uint32_t wB = sb + SM_B + wn * B_SLICE;   // group-shared slice

    // ldmatrix per-lane address offsets (bytes)
    const uint32_t aOff = ((uint32_t)(lane & 15) * A_PITCH + ((lane >> 4) & 1) * 8) * 2;
    const uint32_t bOff = ((uint32_t)(lane >> 4) * 8 + (lane & 7)) * B_PITCHB +
                          ((lane >> 3) & 1) * 16;

    // cp.async role within the wn-group (4 warps = 128 threads):
    //   split = wm&1, row = (wm>>1)*16 + lane>>1 (0..31), k-half = lane&1 (64B)
    const int cpSplit = wm & 1;
    const int cpRowB = ((wm >> 1) << 4) + (lane >> 1);
    const int cpHalf = lane & 1;
    const __half* cpSrcBase = cpSplit ? g_el : g_eh;
    const uint32_t cpDstBase = wB + cpSplit * B_SPLIT + cpRowB * B_PITCHB + cpHalf * 64;

    // ---- prologue: async-load group slice for chunk 0 ----
    {
        const __half* src = cpSrcBase + (size_t)(wn * 32 + cpRowB) * D_DIM + cpHalf * 32;
#pragma unroll
        for (int j = 0; j < 4; j++) cp16(cpDstBase + j * 16, src + j * 8);
        cp_commit();
    }

    // ---- stage x: split to fp16 hi/lo into smem [-2*x] ----
    for (int i = tid; i < M_TILE * 64; i += NTHREADS) {   // 8192 float4
        int row = i >> 6;
        int kq = (i & 63) << 2;
        float4 v = *(const float4*)(x + (size_t)(row0 + row) * D_DIM + kq);
        float ax = -2.0f * v.x, ay = -2.0f * v.y, az = -2.0f * v.z, aw = -2.0f * v.w;
        __half hx = __float2half_rn(ax), hy = __float2half_rn(ay);
        __half hz = __float2half_rn(az), hw = __float2half_rn(aw);
        __half lx = __float2half_rn(ax - __half2float(hx));
        __half ly = __float2half_rn(ay - __half2float(hy));
        __half lz = __float2half_rn(az - __half2float(hz));
        __half lw = __float2half_rn(aw - __half2float(hw));
        half2* dh = (half2*)(smem + SM_A + (size_t)(row * A_PITCH + kq) * 2);
        half2* dl = (half2*)(smem + SM_A + A_SPLIT + (size_t)(row * A_PITCH + kq) * 2);
        dh[0] = __halves2half2(hx, hy);
        dh[1] = __halves2half2(hz, hw);
        dl[0] = __halves2half2(lx, ly);
        dl[1] = __halves2half2(lz, lw);
    }
    __syncthreads();    // A tile visible to all warps

    float acc[2][4][4];       // [mt][nt][quad]
    float e2r[8];
    float bv[4];
    int bi[4];
#pragma unroll
    for (int s = 0; s < 4; s++) { bv[s] = 3.4e38f; bi[s] = 0; }

    // ======== mainloop: wn-groups coupled by named barrier only ========
    for (int c = 0; c < CHUNKS; c++) {
        const int ct = c >> 2, kc = c & 3, buf = c & 1;

        // anti-dependency: all group warps done reading buf^1 (chunk c-1)
        bar_grp(barid);

        // prefetch chunk c+1 (this thread's share) into buf^1
        if (c + 1 < CHUNKS) {
            const int nct = (c + 1) >> 2, nkc = (c + 1) & 3, nbuf = (c + 1) & 1;
            const __half* src = cpSrcBase +
                (size_t)(nct * NT + wn * 32 + cpRowB) * D_DIM + nkc * KC + cpHalf * 32;
            uint32_t dst = cpDstBase + nbuf * B_BUF;
#pragma unroll
            for (int j = 0; j < 4; j++) cp16(dst + j * 16, src + j * 8);
        }
        cp_commit();
        cp_wait1();        // own writes for chunk c complete
        bar_grp(barid);    // group's slice for chunk c now visible

        if (kc == 0) {
#pragma unroll
            for (int mt = 0; mt < 2; mt++)
#pragma unroll
                for (int nt = 0; nt < 4; nt++)
#pragma unroll
                    for (int q = 0; q < 4; q++) acc[mt][nt][q] = 0.0f;
#pragma unroll
            for (int nt = 0; nt < 4; nt++)
#pragma unroll
                for (int q = 0; q < 2; q++)
                    e2r[nt * 2 + q] =
                        __ldg(&g_e2[ct * NT + wn * 32 + nt * 8 + (lane & 3) * 2 + q]);
        }

        // ---- compute: 4 k-steps of 16 ----
#pragma unroll
        for (int ks = 0; ks < 4; ks++) {
            const uint32_t kk0 = (kc * KC + ks * 16) * 2;   // A k byte offset
            const uint32_t kl0 = ks * 32;                   // B k byte offset

            // B fragments: [nt][split][reg], 2 ldmatrix.x4 per split
            uint32_t b[4][2][2];
#pragma unroll
            for (int s = 0; s < 2; s++) {
                uint32_t base = wB + buf * B_BUF + s * B_SPLIT + bOff + kl0;
                ldsm_x4(b[0][s][0], b[0][s][1], b[1][s][0], b[1][s][1], base);
                ldsm_x4(b[2][s][0], b[2][s][1], b[3][s][0], b[3][s][1],
                        base + 16 * B_PITCHB);
            }

            uint32_t a[2][4];
            // --- a = A_hi; sweeps hh then hl (a reused) ---
            {
                uint32_t base = sb + SM_A + aOff + kk0 + wm * (32 * A_PITCH * 2);
#pragma unroll
                for (int mt = 0; mt < 2; mt++)
                    ldsm_x4(a[mt][0], a[mt][1], a[mt][2], a[mt][3],
                            base + mt * (16 * A_PITCH * 2));
            }
#pragma unroll
            for (int mt = 0; mt < 2; mt++)
#pragma unroll
                for (int nt = 0; nt < 4; nt++)
                    mma16816(acc[mt][nt], a[mt], b[nt][0]);
#pragma unroll
            for (int mt = 0; mt < 2; mt++)
#pragma unroll
                for (int nt = 0; nt < 4; nt++)
                    mma16816(acc[mt][nt], a[mt], b[nt][1]);
            // --- a = A_lo; sweep lh ---
            {
                uint32_t base = sb + SM_A + A_SPLIT + aOff + kk0 + wm * (32 * A_PITCH * 2);
#pragma unroll
                for (int mt = 0; mt < 2; mt++)
                    ldsm_x4(a[mt][0], a[mt][1], a[mt][2], a[mt][3],
                            base + mt * (16 * A_PITCH * 2));
            }
#pragma unroll
            for (int mt = 0; mt < 2; mt++)
#pragma unroll
                for (int nt = 0; nt < 4; nt++)
                    mma16816(acc[mt][nt], a[mt], b[nt][0]);
        }

        // ---- epilogue of this code tile: fold e2, running argmin ----
        if (kc == 3) {
#pragma unroll
            for (int mt = 0; mt < 2; mt++)
#pragma unroll
                for (int h = 0; h < 2; h++) {
                    int slot = mt * 2 + h;
#pragma unroll
                    for (int nt = 0; nt < 4; nt++)
#pragma unroll
                        for (int q = 0; q < 2; q++) {
                            float s = e2r[nt * 2 + q] + acc[mt][nt][h * 2 + q];
                            int col = ct * NT + wn * 32 + nt * 8 + (lane & 3) * 2 + q;
                            if (s < bv[slot]) { bv[slot] = s; bi[slot] = col; }
                        }
                }
        }
    }

    // ---- cross-thread argmin reduce (reuse B smem region) ----
    __syncthreads();
    float* redv = (float*)(smem + SM_B);
    int*   redi = (int*)(smem + SM_B + 8192);
#pragma unroll
    for (int slot = 0; slot < 4; slot++) {
        int mt = slot >> 1, h = slot & 1;
        int row_local = wm * 32 + mt * 16 + h * 8 + (lane >> 2);   // 0..127
        int j = wn * 4 + (lane & 3);                               // 0..15
        redv[row_local * 16 + j] = bv[slot];
        redi[row_local * 16 + j] = bi[slot];
    }
    __syncthreads();

    if (tid < M_TILE) {
        float bvv = 3.4e38f;
        int bii = M_CODE;
#pragma unroll
        for (int j = 0; j < 16; j++) {
            float v = redv[tid * 16 + j];
            int i = redi[tid * 16 + j];
            if (v < bvv || (v == bvv && i < bii)) { bvv = v; bii = i; }
        }
        fidx[tid] = bii;
        idx_out[row0 + tid] = (float)bii;
        atomicAdd(&g_counts[bii], 1);
    }
    __syncthreads();

    // ---- gather quantized rows + loss partial ----
    float lsum = 0.0f;
    for (int e = tid; e < M_TILE * D_DIM; e += NTHREADS) {
        int r = e >> 8, k = e & 255;
        float q = embed[(size_t)fidx[r] * D_DIM + k];
        float xv = x[(size_t)(row0 + r) * D_DIM + k];
        quant_out[(size_t)(row0 + r) * D_DIM + k] = q;
        float dd = q - xv;
        lsum += dd * dd;
    }
    float* lred = (float*)(smem + SM_B + 16384);
    lred[tid] = lsum;
    __syncthreads();
#pragma unroll
    for (int s = NTHREADS / 2; s > 0; s >>= 1) {
        if (tid < s) lred[tid] += lred[tid + s];
        __syncthreads();
    }
    if (tid == 0) atomicAdd(&g_loss_sum, lred[0]);
}

// ------------------------------ finalize -------------------------------------
__global__ void vq_finalize_kernel(float* __restrict__ loss_out,
                                   float* __restrict__ perp_out) {
    __shared__ float hred[256];
    int tid = threadIdx.x;
    float h = 0.0f;
    for (int m = tid; m < M_CODE; m += 256) {
        float p = (float)g_counts[m] * (1.0f / (float)N_TOK);
        h += p * logf(p + 1e-10f);
    }
    hred[tid] = h;
    __syncthreads();
#pragma unroll
    for (int s = 128; s > 0; s >>= 1) {
        if (tid < s) hred[tid] += hred[tid + s];
        __syncthreads();
    }
    if (tid == 0) {
        *loss_out = 1.25f * g_loss_sum / (float)((size_t)N_TOK * D_DIM);
        *perp_out = expf(-hred[0]);
    }
}

// ------------------------------ launch ---------------------------------------
extern "C" void kernel_launch(void* const* d_in, const int* in_sizes, int n_in,
                              void* d_out, int out_size) {
    const float* x = (const float*)d_in[0];      // [N, D]
    const float* embed = (const float*)d_in[1];  // [M, D]

    float* out = (float*)d_out;
    float* quant = out;
    float* idxp  = out + (size_t)N_TOK * D_DIM;
    float* lossp = idxp + N_TOK;
    float* perpp = lossp + 1;

    cudaFuncSetAttribute(vq_main_kernel,
                         cudaFuncAttributeMaxDynamicSharedMemorySize, SMEM_TOTAL);

    vq_init_kernel<<<(M_CODE + 255) / 256, 256>>>();
    vq_e2_kernel<<<(M_CODE + 255) / 256, 256>>>(embed);
    vq_split_kernel<<<(M_CODE * D_DIM / 4 + 255) / 256, 256>>>(embed);
    vq_main_kernel<<<N_TOK / M_TILE, NTHREADS, SMEM_TOTAL>>>(x, embed, quant, idxp);
    vq_finalize_kernel<<<1, 256>>>(lossp, perpp);
}

// round 13
// speedup vs baseline: 1.4516x; 1.4516x over previous
#include <cuda_runtime.h>
#include <cuda_fp16.h>
#include <math.h>
#include <stdint.h>

#define N_TOK 32768
#define M_CODE 4096
#define D_DIM 256
#define M_TILE 128                    // tokens per CTA
#define NT 128                        // codes per tile
#define CT_COUNT (M_CODE / NT)        // 32
#define CHUNKS (CT_COUNT * 8)         // 256 chunks of 32 k
#define NTHREADS 512
#define DELTA 0.05f                   // rescore margin (≈45 sigma of hh error)

// ---------------- smem layout (bytes) ----------------
#define A_PITCH 264                    // halves per row (256 + 8 pad)
#define SM_A    0                      // hi split only: 128 * 264 * 2 = 67584
#define SM_B    67584                  // 8 pair-shared hi slices
#define B_SLICE 2560                   // per wn slice (2 buf x 1280)
#define B_BUF   1280                   // 16 rows x 80 B
#define B_PITCH 40                     // halves per row (32 + 8 pad)
#define SM_FIDX 88064                  // 128 ints
#define SMEM_TOTAL 88576
// post-mainloop overlays: redv @0 (32KB), redi @32768 (32KB), lred @SM_B

__device__ float g_e2[M_CODE];
__device__ int   g_counts[M_CODE];
__device__ float g_loss_sum;
__device__ __align__(16) __half g_eh[M_CODE * D_DIM];

// ---------------------------- helpers ----------------------------------
__device__ __forceinline__ uint32_t smem_u32(const void* p) {
    uint32_t a;
    asm("{ .reg .u64 t; cvta.to.shared.u64 t, %1; cvt.u32.u64 %0, t; }"
        : "=r"(a) : "l"(p));
    return a;
}
__device__ __forceinline__ void ldsm_x4(uint32_t& r0, uint32_t& r1,
                                        uint32_t& r2, uint32_t& r3, uint32_t a) {
    asm volatile("ldmatrix.sync.aligned.m8n8.x4.shared.b16 {%0,%1,%2,%3}, [%4];"
                 : "=r"(r0), "=r"(r1), "=r"(r2), "=r"(r3) : "r"(a));
}
__device__ __forceinline__ void cp16(uint32_t dst, const void* src) {
    asm volatile("cp.async.cg.shared.global [%0], [%1], 16;"
                 :: "r"(dst), "l"(src) : "memory");
}
__device__ __forceinline__ void cp_commit() {
    asm volatile("cp.async.commit_group;" ::: "memory");
}
__device__ __forceinline__ void cp_wait1() {
    asm volatile("cp.async.wait_group 1;" ::: "memory");
}
__device__ __forceinline__ void bar_pair(int id) {
    asm volatile("bar.sync %0, 64;" :: "r"(id) : "memory");
}
__device__ __forceinline__ void mma16816(float* c, const uint32_t* a, const uint32_t* b) {
    asm volatile(
        "mma.sync.aligned.m16n8k16.row.col.f32.f16.f16.f32 "
        "{%0,%1,%2,%3}, {%4,%5,%6,%7}, {%8,%9}, {%0,%1,%2,%3};"
        : "+f"(c[0]), "+f"(c[1]), "+f"(c[2]), "+f"(c[3])
        : "r"(a[0]), "r"(a[1]), "r"(a[2]), "r"(a[3]), "r"(b[0]), "r"(b[1]));
}

// ----------------------------- small kernels --------------------------------
__global__ void vq_init_kernel() {
    int t = blockIdx.x * blockDim.x + threadIdx.x;
    if (t < M_CODE) g_counts[t] = 0;
    if (t == 0) g_loss_sum = 0.0f;
}
__global__ void vq_e2_kernel(const float* __restrict__ embed) {
    int m = blockIdx.x * blockDim.x + threadIdx.x;
    if (m >= M_CODE) return;
    const float4* row = reinterpret_cast<const float4*>(embed + (size_t)m * D_DIM);
    float s = 0.0f;
#pragma unroll
    for (int i = 0; i < D_DIM / 4; i++) {
        float4 v = row[i];
        s += v.x * v.x + v.y * v.y + v.z * v.z + v.w * v.w;
    }
    g_e2[m] = s;
}
__global__ void vq_split_kernel(const float* __restrict__ embed) {
    int i = blockIdx.x * blockDim.x + threadIdx.x;   // one float4 each
    if (i >= M_CODE * D_DIM / 4) return;
    float4 v = reinterpret_cast<const float4*>(embed)[i];
    half2* ph = reinterpret_cast<half2*>(g_eh);
    ph[i * 2 + 0] = __halves2half2(__float2half_rn(v.x), __float2half_rn(v.y));
    ph[i * 2 + 1] = __halves2half2(__float2half_rn(v.z), __float2half_rn(v.w));
}

// ------------------------------ main kernel ---------------------------------
__global__ __launch_bounds__(NTHREADS, 1)
void vq_main_kernel(const float* __restrict__ x,
                    const float* __restrict__ embed,
                    float* __restrict__ quant_out,
                    float* __restrict__ idx_out) {
    extern __shared__ char smem[];
    const uint32_t sb = smem_u32(smem);
    const int tid = threadIdx.x;
    const int lane = tid & 31;
    const int wid = tid >> 5;
    const int wn = wid & 7;              // col stripe wn*16 .. +16
    const int wm = wid >> 3;             // row half wm*64 .. +64
    const int row0 = blockIdx.x * M_TILE;
    const int barid = wn + 1;

    int* fidx = (int*)(smem + SM_FIDX);
    const uint32_t wB = sb + SM_B + wn * B_SLICE;   // pair-shared hi slice

    // ldmatrix per-lane address offsets (bytes)
    const uint32_t aOff = ((uint32_t)(lane & 15) * A_PITCH + ((lane >> 4) & 1) * 8) * 2;
    const uint32_t bOff = (((uint32_t)(lane >> 4) * 8 + (lane & 7)) * B_PITCH +
                           ((lane >> 3) & 1) * 8) * 2;

    // cp.async role within pair: 64 threads load 16 rows x 64 B
    const int cpP = wm * 32 + lane;        // 0..63
    const int cpRow = cpP >> 2;            // 0..15
    const int cpSeg = cpP & 3;             // 16B segment
    const uint32_t cpDst = wB + cpRow * (B_PITCH * 2) + cpSeg * 16;

    // ---- prologue: async-load pair slice for chunk 0 ----
    cp16(cpDst, g_eh + (size_t)(wn * 16 + cpRow) * D_DIM + cpSeg * 8);
    cp_commit();

    // ---- stage x: hi split of (-2x) into smem ----
    for (int i = tid; i < M_TILE * 64; i += NTHREADS) {   // 8192 float4
        int row = i >> 6;
        int kq = (i & 63) << 2;
        float4 v = *(const float4*)(x + (size_t)(row0 + row) * D_DIM + kq);
        half2* dh = (half2*)(smem + SM_A + (size_t)(row * A_PITCH + kq) * 2);
        dh[0] = __halves2half2(__float2half_rn(-2.0f * v.x), __float2half_rn(-2.0f * v.y));
        dh[1] = __halves2half2(__float2half_rn(-2.0f * v.z), __float2half_rn(-2.0f * v.w));
    }
    __syncthreads();

    float acc[4][2][4];       // [mt][nt][quad]
    float e2r[4];
    float bv1[8], bv2[8];
    int bi1[8], bi2[8];
#pragma unroll
    for (int s = 0; s < 8; s++) {
        bv1[s] = 3.4e38f; bv2[s] = 3.4e38f; bi1[s] = 0; bi2[s] = 0;
    }

    // ======== mainloop: hh pass only ========
    for (int c = 0; c < CHUNKS; c++) {
        const int ct = c >> 3, kc = c & 7, buf = c & 1;

        bar_pair(barid);   // pair done reading buf^1 (chunk c-1)

        if (c + 1 < CHUNKS) {
            const int nct = (c + 1) >> 3, nkc = (c + 1) & 7, nbuf = (c + 1) & 1;
            cp16(cpDst + nbuf * B_BUF,
                 g_eh + (size_t)(nct * NT + wn * 16 + cpRow) * D_DIM + nkc * 32 + cpSeg * 8);
        }
        cp_commit();
        cp_wait1();
        bar_pair(barid);   // pair slice for chunk c visible

        if (kc == 0) {
#pragma unroll
            for (int mt = 0; mt < 4; mt++)
#pragma unroll
                for (int nt = 0; nt < 2; nt++)
#pragma unroll
                    for (int q = 0; q < 4; q++) acc[mt][nt][q] = 0.0f;
#pragma unroll
            for (int nt = 0; nt < 2; nt++)
#pragma unroll
                for (int q = 0; q < 2; q++)
                    e2r[nt * 2 + q] =
                        __ldg(&g_e2[ct * NT + wn * 16 + nt * 8 + (lane & 3) * 2 + q]);
        }

        // ---- compute: 2 k-steps of 16, hh only ----
#pragma unroll
        for (int ks = 0; ks < 2; ks++) {
            const uint32_t kk0 = (kc * 32 + ks * 16) * 2;
            const uint32_t kl0 = (ks * 16) * 2;

            uint32_t b[2][2];
            {
                uint32_t base = wB + buf * B_BUF + bOff + kl0;
                ldsm_x4(b[0][0], b[0][1], b[1][0], b[1][1], base);
            }
            uint32_t a[4][4];
            {
                uint32_t base = sb + SM_A + aOff + kk0 + wm * (64 * A_PITCH * 2);
#pragma unroll
                for (int mt = 0; mt < 4; mt++)
                    ldsm_x4(a[mt][0], a[mt][1], a[mt][2], a[mt][3],
                            base + mt * (16 * A_PITCH * 2));
            }
#pragma unroll
            for (int mt = 0; mt < 4; mt++)
#pragma unroll
                for (int nt = 0; nt < 2; nt++)
                    mma16816(acc[mt][nt], a[mt], b[nt]);
        }

        // ---- epilogue: fold e2, best-2 per cell ----
        if (kc == 7) {
#pragma unroll
            for (int mt = 0; mt < 4; mt++)
#pragma unroll
                for (int h = 0; h < 2; h++) {
                    int slot = mt * 2 + h;
#pragma unroll
                    for (int nt = 0; nt < 2; nt++)
#pragma unroll
                        for (int q = 0; q < 2; q++) {
                            float s = e2r[nt * 2 + q] + acc[mt][nt][h * 2 + q];
                            int col = ct * NT + wn * 16 + nt * 8 + (lane & 3) * 2 + q;
                            if (s < bv1[slot]) {
                                bv2[slot] = bv1[slot]; bi2[slot] = bi1[slot];
                                bv1[slot] = s; bi1[slot] = col;
                            } else if (s < bv2[slot]) {
                                bv2[slot] = s; bi2[slot] = col;
                            }
                        }
                }
        }
    }

    // ---- dump best-2 candidates (overlay A smem region) ----
    __syncthreads();
    float* redv = (float*)(smem);            // [128][64]
    int*   redi = (int*)(smem + 32768);      // [128][64]
#pragma unroll
    for (int slot = 0; slot < 8; slot++) {
        int mt = slot >> 1, h = slot & 1;
        int row_local = wm * 64 + mt * 16 + h * 8 + (lane >> 2);   // 0..127
        int j = wn * 4 + (lane & 3);                               // 0..31
        redv[row_local * 64 + j * 2 + 0] = bv1[slot];
        redv[row_local * 64 + j * 2 + 1] = bv2[slot];
        redi[row_local * 64 + j * 2 + 0] = bi1[slot];
        redi[row_local * 64 + j * 2 + 1] = bi2[slot];
    }
    __syncthreads();

    // ---- exact rescore: warp per token, candidates within DELTA of approx min ----
    for (int t = wid; t < M_TILE; t += 16) {
        float v0 = redv[t * 64 + lane];
        float v1 = redv[t * 64 + 32 + lane];
        float vmin = fminf(v0, v1);
#pragma unroll
        for (int o = 16; o > 0; o >>= 1)
            vmin = fminf(vmin, __shfl_xor_sync(0xFFFFFFFFu, vmin, o));
        const float thresh = vmin + DELTA;

        float bestv = 3.4e38f;
        int besti = M_CODE;
        const float* xr = x + (size_t)(row0 + t) * D_DIM;
        for (int j = 0; j < 64; j++) {
            float v = redv[t * 64 + j];      // warp-uniform
            if (v <= thresh) {
                int cidx = redi[t * 64 + j];
                const float* er = embed + (size_t)cidx * D_DIM;
                float dot = 0.0f;
#pragma unroll
                for (int kk = 0; kk < 8; kk++)
                    dot += xr[lane + kk * 32] * er[lane + kk * 32];
#pragma unroll
                for (int o = 16; o > 0; o >>= 1)
                    dot += __shfl_xor_sync(0xFFFFFFFFu, dot, o);
                float s = __ldg(&g_e2[cidx]) - 2.0f * dot;
                if (s < bestv || (s == bestv && cidx < besti)) { bestv = s; besti = cidx; }
            }
        }
        if (lane == 0) {
            fidx[t] = besti;
            idx_out[row0 + t] = (float)besti;
            atomicAdd(&g_counts[besti], 1);
        }
    }
    __syncthreads();

    // ---- gather quantized rows + loss partial ----
    float lsum = 0.0f;
    for (int e = tid; e < M_TILE * D_DIM; e += NTHREADS) {
        int r = e >> 8, k = e & 255;
        float q = embed[(size_t)fidx[r] * D_DIM + k];
        float xv = x[(size_t)(row0 + r) * D_DIM + k];
        quant_out[(size_t)(row0 + r) * D_DIM + k] = q;
        float dd = q - xv;
        lsum += dd * dd;
    }
    float* lred = (float*)(smem + SM_B);
    lred[tid] = lsum;
    __syncthreads();
#pragma unroll
    for (int s = NTHREADS / 2; s > 0; s >>= 1) {
        if (tid < s) lred[tid] += lred[tid + s];
        __syncthreads();
    }
    if (tid == 0) atomicAdd(&g_loss_sum, lred[0]);
}

// ------------------------------ finalize -------------------------------------
__global__ void vq_finalize_kernel(float* __restrict__ loss_out,
                                   float* __restrict__ perp_out) {
    __shared__ float hred[256];
    int tid = threadIdx.x;
    float h = 0.0f;
    for (int m = tid; m < M_CODE; m += 256) {
        float p = (float)g_counts[m] * (1.0f / (float)N_TOK);
        h += p * logf(p + 1e-10f);
    }
    hred[tid] = h;
    __syncthreads();
#pragma unroll
    for (int s = 128; s > 0; s >>= 1) {
        if (tid < s) hred[tid] += hred[tid + s];
        __syncthreads();
    }
    if (tid == 0) {
        *loss_out = 1.25f * g_loss_sum / (float)((size_t)N_TOK * D_DIM);
        *perp_out = expf(-hred[0]);
    }
}

// ------------------------------ launch ---------------------------------------
extern "C" void kernel_launch(void* const* d_in, const int* in_sizes, int n_in,
                              void* d_out, int out_size) {
    const float* x = (const float*)d_in[0];      // [N, D]
    const float* embed = (const float*)d_in[1];  // [M, D]

    float* out = (float*)d_out;
    float* quant = out;
    float* idxp  = out + (size_t)N_TOK * D_DIM;
    float* lossp = idxp + N_TOK;
    float* perpp = lossp + 1;

    cudaFuncSetAttribute(vq_main_kernel,
                         cudaFuncAttributeMaxDynamicSharedMemorySize, SMEM_TOTAL);

    vq_init_kernel<<<(M_CODE + 255) / 256, 256>>>();
    vq_e2_kernel<<<(M_CODE + 255) / 256, 256>>>(embed);
    vq_split_kernel<<<(M_CODE * D_DIM / 4 + 255) / 256, 256>>>(embed);
    vq_main_kernel<<<N_TOK / M_TILE, NTHREADS, SMEM_TOTAL>>>(x, embed, quant, idxp);
    vq_finalize_kernel<<<1, 256>>>(lossp, perpp);
}

// round 14
// speedup vs baseline: 1.5373x; 1.0590x over previous
#include <cuda_runtime.h>
#include <cuda_fp16.h>
#include <math.h>
#include <stdint.h>

#define N_TOK 32768
#define M_CODE 4096
#define D_DIM 256
#define M_TILE 128                    // tokens per CTA
#define NT 128                        // codes per tile
#define CT_COUNT (M_CODE / NT)        // 32
#define KC 64                         // k per chunk
#define CHUNKS (CT_COUNT * 4)         // 128 chunks of 64 k
#define NTHREADS 512
#define DELTA 0.05f                   // rescore margin (≈45 sigma of hh error)

// ---------------- smem layout (bytes) ----------------
#define A_PITCH 264                    // halves per row (256 + 8 pad)
#define SM_A    0                      // hi split only: 128 * 264 * 2 = 67584
#define SM_B    67584                  // 16 per-warp private hi slices
#define B_PITCHB 144                   // bytes per row (128 + 16 pad)
#define B_BUF   2304                   // 16 rows x 144 B
#define BW_WARP 4608                   // 2 buffers
#define SM_FIDX 141312                 // 128 ints
#define SMEM_TOTAL 141824
// post-mainloop overlays: redv @0 (32KB), redi @32768 (32KB), lred @SM_B

__device__ float g_e2[M_CODE];
__device__ int   g_counts[M_CODE];
__device__ float g_loss_sum;
__device__ __align__(16) __half g_eh[M_CODE * D_DIM];

// ---------------------------- helpers ----------------------------------
__device__ __forceinline__ uint32_t smem_u32(const void* p) {
    uint32_t a;
    asm("{ .reg .u64 t; cvta.to.shared.u64 t, %1; cvt.u32.u64 %0, t; }"
        : "=r"(a) : "l"(p));
    return a;
}
__device__ __forceinline__ void ldsm_x4(uint32_t& r0, uint32_t& r1,
                                        uint32_t& r2, uint32_t& r3, uint32_t a) {
    asm volatile("ldmatrix.sync.aligned.m8n8.x4.shared.b16 {%0,%1,%2,%3}, [%4];"
                 : "=r"(r0), "=r"(r1), "=r"(r2), "=r"(r3) : "r"(a));
}
__device__ __forceinline__ void cp16(uint32_t dst, const void* src) {
    asm volatile("cp.async.cg.shared.global [%0], [%1], 16;"
                 :: "r"(dst), "l"(src) : "memory");
}
__device__ __forceinline__ void cp_commit() {
    asm volatile("cp.async.commit_group;" ::: "memory");
}
__device__ __forceinline__ void cp_wait1() {
    asm volatile("cp.async.wait_group 1;" ::: "memory");
}
__device__ __forceinline__ void mma16816(float* c, const uint32_t* a, const uint32_t* b) {
    asm volatile(
        "mma.sync.aligned.m16n8k16.row.col.f32.f16.f16.f32 "
        "{%0,%1,%2,%3}, {%4,%5,%6,%7}, {%8,%9}, {%0,%1,%2,%3};"
        : "+f"(c[0]), "+f"(c[1]), "+f"(c[2]), "+f"(c[3])
        : "r"(a[0]), "r"(a[1]), "r"(a[2]), "r"(a[3]), "r"(b[0]), "r"(b[1]));
}

// ----------------------------- small kernels --------------------------------
__global__ void vq_init_kernel() {
    int t = blockIdx.x * blockDim.x + threadIdx.x;
    if (t < M_CODE) g_counts[t] = 0;
    if (t == 0) g_loss_sum = 0.0f;
}
__global__ void vq_e2_kernel(const float* __restrict__ embed) {
    int m = blockIdx.x * blockDim.x + threadIdx.x;
    if (m >= M_CODE) return;
    const float4* row = reinterpret_cast<const float4*>(embed + (size_t)m * D_DIM);
    float s = 0.0f;
#pragma unroll
    for (int i = 0; i < D_DIM / 4; i++) {
        float4 v = row[i];
        s += v.x * v.x + v.y * v.y + v.z * v.z + v.w * v.w;
    }
    g_e2[m] = s;
}
__global__ void vq_split_kernel(const float* __restrict__ embed) {
    int i = blockIdx.x * blockDim.x + threadIdx.x;   // one float4 each
    if (i >= M_CODE * D_DIM / 4) return;
    float4 v = reinterpret_cast<const float4*>(embed)[i];
    half2* ph = reinterpret_cast<half2*>(g_eh);
    ph[i * 2 + 0] = __halves2half2(__float2half_rn(v.x), __float2half_rn(v.y));
    ph[i * 2 + 1] = __halves2half2(__float2half_rn(v.z), __float2half_rn(v.w));
}

// ------------------------------ main kernel ---------------------------------
__global__ __launch_bounds__(NTHREADS, 1)
void vq_main_kernel(const float* __restrict__ x,
                    const float* __restrict__ embed,
                    float* __restrict__ quant_out,
                    float* __restrict__ idx_out) {
    extern __shared__ char smem[];
    const uint32_t sb = smem_u32(smem);
    const int tid = threadIdx.x;
    const int lane = tid & 31;
    const int wid = tid >> 5;
    const int wn = wid & 7;              // col stripe wn*16 .. +16
    const int wm = wid >> 3;             // row half wm*64 .. +64
    const int row0 = blockIdx.x * M_TILE;

    int* fidx = (int*)(smem + SM_FIDX);
    const uint32_t wB = sb + SM_B + wid * BW_WARP;   // warp-private hi slice

    // ldmatrix per-lane address offsets (bytes)
    const uint32_t aOff = ((uint32_t)(lane & 15) * A_PITCH + ((lane >> 4) & 1) * 8) * 2;
    const uint32_t bOff = ((uint32_t)(lane >> 4) * 8 + (lane & 7)) * B_PITCHB +
                          ((lane >> 3) & 1) * 16;

    // cp.async role: 32 lanes load 16 rows x 128 B (64 B per lane)
    const int cpRow = lane >> 1;          // 0..15
    const int cpSeg = lane & 1;           // 64 B half of the 128 B row
    const uint32_t cpDst = wB + cpRow * B_PITCHB + cpSeg * 64;

    // ---- prologue: async-load own slice for chunk 0 ----
    {
        const __half* src = g_eh + (size_t)(wn * 16 + cpRow) * D_DIM + cpSeg * 32;
#pragma unroll
        for (int j = 0; j < 4; j++) cp16(cpDst + j * 16, src + j * 8);
        cp_commit();
    }

    // ---- stage x: hi split of (-2x) into smem ----
    for (int i = tid; i < M_TILE * 64; i += NTHREADS) {   // 8192 float4
        int row = i >> 6;
        int kq = (i & 63) << 2;
        float4 v = *(const float4*)(x + (size_t)(row0 + row) * D_DIM + kq);
        half2* dh = (half2*)(smem + SM_A + (size_t)(row * A_PITCH + kq) * 2);
        dh[0] = __halves2half2(__float2half_rn(-2.0f * v.x), __float2half_rn(-2.0f * v.y));
        dh[1] = __halves2half2(__float2half_rn(-2.0f * v.z), __float2half_rn(-2.0f * v.w));
    }
    __syncthreads();    // the ONLY pre-loop barrier

    float acc[4][2][4];       // [mt][nt][quad]
    float e2r[4];
    float bv1[8], bv2[8];
    int bi1[8], bi2[8];
#pragma unroll
    for (int s = 0; s < 8; s++) {
        bv1[s] = 3.4e38f; bv2[s] = 3.4e38f; bi1[s] = 0; bi2[s] = 0;
    }

    // ======== barrier-free mainloop: hh pass, 64-k chunks ========
    for (int c = 0; c < CHUNKS; c++) {
        const int ct = c >> 2, kc = c & 3, buf = c & 1;

        // per-warp prefetch of chunk c+1 into the other buffer
        if (c + 1 < CHUNKS) {
            const int nct = (c + 1) >> 2, nkc = (c + 1) & 3, nbuf = (c + 1) & 1;
            const __half* src = g_eh +
                (size_t)(nct * NT + wn * 16 + cpRow) * D_DIM + nkc * KC + cpSeg * 32;
            uint32_t dst = cpDst + nbuf * B_BUF;
#pragma unroll
            for (int j = 0; j < 4; j++) cp16(dst + j * 16, src + j * 8);
        }
        cp_commit();
        cp_wait1();        // chunk c's slice resident (per-warp ordering)

        if (kc == 0) {
#pragma unroll
            for (int mt = 0; mt < 4; mt++)
#pragma unroll
                for (int nt = 0; nt < 2; nt++)
#pragma unroll
                    for (int q = 0; q < 4; q++) acc[mt][nt][q] = 0.0f;
#pragma unroll
            for (int nt = 0; nt < 2; nt++)
#pragma unroll
                for (int q = 0; q < 2; q++)
                    e2r[nt * 2 + q] =
                        __ldg(&g_e2[ct * NT + wn * 16 + nt * 8 + (lane & 3) * 2 + q]);
        }

        // ---- compute: 4 k-steps of 16, hh only ----
#pragma unroll
        for (int ks = 0; ks < 4; ks++) {
            const uint32_t kk0 = (kc * KC + ks * 16) * 2;   // A k byte offset
            const uint32_t kl0 = ks * 32;                   // B k byte offset

            uint32_t b[2][2];
            ldsm_x4(b[0][0], b[0][1], b[1][0], b[1][1],
                    wB + buf * B_BUF + bOff + kl0);

            uint32_t a[4][4];
            {
                uint32_t base = sb + SM_A + aOff + kk0 + wm * (64 * A_PITCH * 2);
#pragma unroll
                for (int mt = 0; mt < 4; mt++)
                    ldsm_x4(a[mt][0], a[mt][1], a[mt][2], a[mt][3],
                            base + mt * (16 * A_PITCH * 2));
            }
#pragma unroll
            for (int mt = 0; mt < 4; mt++)
#pragma unroll
                for (int nt = 0; nt < 2; nt++)
                    mma16816(acc[mt][nt], a[mt], b[nt]);
        }

        // ---- epilogue: fold e2, best-2 per cell ----
        if (kc == 3) {
#pragma unroll
            for (int mt = 0; mt < 4; mt++)
#pragma unroll
                for (int h = 0; h < 2; h++) {
                    int slot = mt * 2 + h;
#pragma unroll
                    for (int nt = 0; nt < 2; nt++)
#pragma unroll
                        for (int q = 0; q < 2; q++) {
                            float s = e2r[nt * 2 + q] + acc[mt][nt][h * 2 + q];
                            int col = ct * NT + wn * 16 + nt * 8 + (lane & 3) * 2 + q;
                            if (s < bv1[slot]) {
                                bv2[slot] = bv1[slot]; bi2[slot] = bi1[slot];
                                bv1[slot] = s; bi1[slot] = col;
                            } else if (s < bv2[slot]) {
                                bv2[slot] = s; bi2[slot] = col;
                            }
                        }
                }
        }
    }

    // ---- dump best-2 candidates (overlay A smem region) ----
    __syncthreads();
    float* redv = (float*)(smem);            // [128][64]
    int*   redi = (int*)(smem + 32768);      // [128][64]
#pragma unroll
    for (int slot = 0; slot < 8; slot++) {
        int mt = slot >> 1, h = slot & 1;
        int row_local = wm * 64 + mt * 16 + h * 8 + (lane >> 2);   // 0..127
        int j = wn * 4 + (lane & 3);                               // 0..31
        redv[row_local * 64 + j * 2 + 0] = bv1[slot];
        redv[row_local * 64 + j * 2 + 1] = bv2[slot];
        redi[row_local * 64 + j * 2 + 0] = bi1[slot];
        redi[row_local * 64 + j * 2 + 1] = bi2[slot];
    }
    __syncthreads();

    // ---- exact rescore: warp per token, candidates within DELTA of approx min ----
    for (int t = wid; t < M_TILE; t += 16) {
        float v0 = redv[t * 64 + lane];
        float v1 = redv[t * 64 + 32 + lane];
        float vmin = fminf(v0, v1);
#pragma unroll
        for (int o = 16; o > 0; o >>= 1)
            vmin = fminf(vmin, __shfl_xor_sync(0xFFFFFFFFu, vmin, o));
        const float thresh = vmin + DELTA;

        float bestv = 3.4e38f;
        int besti = M_CODE;
        const float* xr = x + (size_t)(row0 + t) * D_DIM;
        for (int j = 0; j < 64; j++) {
            float v = redv[t * 64 + j];      // warp-uniform
            if (v <= thresh) {
                int cidx = redi[t * 64 + j];
                const float* er = embed + (size_t)cidx * D_DIM;
                float dot = 0.0f;
#pragma unroll
                for (int kk = 0; kk < 8; kk++)
                    dot += xr[lane + kk * 32] * er[lane + kk * 32];
#pragma unroll
                for (int o = 16; o > 0; o >>= 1)
                    dot += __shfl_xor_sync(0xFFFFFFFFu, dot, o);
                float s = __ldg(&g_e2[cidx]) - 2.0f * dot;
                if (s < bestv || (s == bestv && cidx < besti)) { bestv = s; besti = cidx; }
            }
        }
        if (lane == 0) {
            fidx[t] = besti;
            idx_out[row0 + t] = (float)besti;
            atomicAdd(&g_counts[besti], 1);
        }
    }
    __syncthreads();

    // ---- gather quantized rows + loss partial ----
    float lsum = 0.0f;
    for (int e = tid; e < M_TILE * D_DIM; e += NTHREADS) {
        int r = e >> 8, k = e & 255;
        float q = embed[(size_t)fidx[r] * D_DIM + k];
        float xv = x[(size_t)(row0 + r) * D_DIM + k];
        quant_out[(size_t)(row0 + r) * D_DIM + k] = q;
        float dd = q - xv;
        lsum += dd * dd;
    }
    float* lred = (float*)(smem + SM_B);
    lred[tid] = lsum;
    __syncthreads();
#pragma unroll
    for (int s = NTHREADS / 2; s > 0; s >>= 1) {
        if (tid < s) lred[tid] += lred[tid + s];
        __syncthreads();
    }
    if (tid == 0) atomicAdd(&g_loss_sum, lred[0]);
}

// ------------------------------ finalize -------------------------------------
__global__ void vq_finalize_kernel(float* __restrict__ loss_out,
                                   float* __restrict__ perp_out) {
    __shared__ float hred[256];
    int tid = threadIdx.x;
    float h = 0.0f;
    for (int m = tid; m < M_CODE; m += 256) {
        float p = (float)g_counts[m] * (1.0f / (float)N_TOK);
        h += p * logf(p + 1e-10f);
    }
    hred[tid] = h;
    __syncthreads();
#pragma unroll
    for (int s = 128; s > 0; s >>= 1) {
        if (tid < s) hred[tid] += hred[tid + s];
        __syncthreads();
    }
    if (tid == 0) {
        *loss_out = 1.25f * g_loss_sum / (float)((size_t)N_TOK * D_DIM);
        *perp_out = expf(-hred[0]);
    }
}

// ------------------------------ launch ---------------------------------------
extern "C" void kernel_launch(void* const* d_in, const int* in_sizes, int n_in,
                              void* d_out, int out_size) {
    const float* x = (const float*)d_in[0];      // [N, D]
    const float* embed = (const float*)d_in[1];  // [M, D]

    float* out = (float*)d_out;
    float* quant = out;
    float* idxp  = out + (size_t)N_TOK * D_DIM;
    float* lossp = idxp + N_TOK;
    float* perpp = lossp + 1;

    cudaFuncSetAttribute(vq_main_kernel,
                         cudaFuncAttributeMaxDynamicSharedMemorySize, SMEM_TOTAL);

    vq_init_kernel<<<(M_CODE + 255) / 256, 256>>>();
    vq_e2_kernel<<<(M_CODE + 255) / 256, 256>>>(embed);
    vq_split_kernel<<<(M_CODE * D_DIM / 4 + 255) / 256, 256>>>(embed);
    vq_main_kernel<<<N_TOK / M_TILE, NTHREADS, SMEM_TOTAL>>>(x, embed, quant, idxp);
    vq_finalize_kernel<<<1, 256>>>(lossp, perpp);
}